// round 4
// baseline (speedup 1.0000x reference)
#include <cuda_runtime.h>
#include <math.h>

#define HWSZ 16384
#define CHN  256
#define KQ   1024
#define NQ   2048
#define HSLOTS 256

// ---------------- device scratch (static, allocation-free) ----------------
__device__ float    g_val[(size_t)2 * 4 * HWSZ * CHN];   // [b*4+f][y][x][c], +time_pos
__device__ unsigned g_keys[2 * HWSZ];
__device__ int      g_ind[NQ];
__device__ float    g_q[NQ * CHN];
__device__ float    g_qpos[NQ * CHN];
__device__ float    g_so[NQ * CHN];       // sampling offsets (post-GEMM)
__device__ float    g_aw[NQ * 128];       // attention weights (post-softmax)
__device__ float    g_agg[(size_t)NQ * 8 * CHN];  // per-(q,head) aggregated value vec
__device__ float    g_bw[NQ * 8];         // per-(q,head) sum of valid coefs

__device__ __forceinline__ float gelu_tanh(float v) {
    float c = 0.7978845608028654f * (v + 0.044715f * v * v * v);
    return 0.5f * v * (1.0f + tanhf(c));
}

// ---------------- K1: transpose x[b,f,c,y,x] -> g_val[b,f,y,x,c] (+time_pos) ----------------
__global__ void k_transpose(const float* __restrict__ x, const float* __restrict__ tp) {
    __shared__ float tile[32][33];
    int xt = blockIdx.x * 32;
    int ct = blockIdx.y * 32;
    int z  = blockIdx.z;
    int y  = z & 127;
    int bf = z >> 7;
    int f  = bf & 3;
    int tx = threadIdx.x, ty = threadIdx.y;
    tile[ty][tx] = x[((size_t)(bf * CHN + ct + ty) * 128 + y) * 128 + xt + tx];
    __syncthreads();
    g_val[((size_t)(bf * 128 + y) * 128 + xt + ty) * CHN + ct + tx] =
        tile[tx][ty] + tp[f * CHN + ct + tx];
}

// ---------------- K2a: channel-max score -> orderable keys (parallel) ----------------
__global__ __launch_bounds__(1024) void k_score(const float* __restrict__ hm) {
    int i = blockIdx.x * 1024 + threadIdx.x;      // 0 .. 32767
    int b = i >> 14, cell = i & (HWSZ - 1);
    const float* hb = hm + (size_t)b * 10 * HWSZ + cell;
    float m = hb[0];
    #pragma unroll
    for (int c = 1; c < 10; c++) m = fmaxf(m, hb[c * HWSZ]);
    unsigned u = __float_as_uint(m);
    u = (u & 0x80000000u) ? ~u : (u | 0x80000000u);
    g_keys[i] = u;
}

// ---------------- K2b: radix top-1024 per batch ----------------
__global__ __launch_bounds__(1024) void k_topk() {
    int b = blockIdx.x, t = threadIdx.x;
    __shared__ unsigned hist[256];
    __shared__ unsigned sh[4];

    unsigned prefix = 0, r = KQ;
    for (int byte = 3; byte >= 0; byte--) {
        if (t < 256) hist[t] = 0;
        __syncthreads();
        int sh8 = byte * 8;
        unsigned pm = (byte == 3) ? 0u : (0xFFFFFFFFu << (8 * (byte + 1)));
        for (int i = t; i < HWSZ; i += 1024) {
            unsigned k = g_keys[b * HWSZ + i];
            if ((k & pm) == (prefix & pm)) atomicAdd(&hist[(k >> sh8) & 255u], 1u);
        }
        __syncthreads();
        if (t == 0) {
            unsigned cum = 0, d = 0;
            for (int dd = 255; dd >= 0; dd--) {
                if (cum + hist[dd] >= r) { d = (unsigned)dd; break; }
                cum += hist[dd];
            }
            sh[0] = d; sh[1] = r - cum;
        }
        __syncthreads();
        prefix |= sh[0] << sh8;
        r = sh[1];
        __syncthreads();
    }
    unsigned T = prefix;
    if (t == 0) { sh[2] = 0; sh[3] = 0; }
    __syncthreads();
    for (int i = t; i < HWSZ; i += 1024)
        if (g_keys[b * HWSZ + i] > T) atomicAdd(&sh[2], 1u);
    __syncthreads();
    unsigned cgt = sh[2];
    unsigned neq = KQ - cgt;
    __syncthreads();
    if (t == 0) sh[2] = 0;
    __syncthreads();
    for (int i = t; i < HWSZ; i += 1024) {
        unsigned k = g_keys[b * HWSZ + i];
        if (k > T) {
            unsigned s = atomicAdd(&sh[2], 1u);
            g_ind[b * KQ + s] = i;
        } else if (k == T) {
            unsigned e = atomicAdd(&sh[3], 1u);
            if (e < neq) g_ind[b * KQ + cgt + e] = i;
        }
    }
}

// ---------------- K3: query-init MLP + positional embed gather ----------------
__global__ __launch_bounds__(256) void k_qinit(
    const float* __restrict__ preds,
    const float* __restrict__ W1, const float* __restrict__ b1,
    const float* __restrict__ W2, const float* __restrict__ b2,
    const float* __restrict__ rowe, const float* __restrict__ cole) {
    __shared__ float q0S[8][70];
    __shared__ float hidS[8][CHN];
    __shared__ int   indS[8];
    int t = threadIdx.x;
    int qg0 = blockIdx.x * 8;
    if (t < 8) indS[t] = g_ind[qg0 + t];
    __syncthreads();
    for (int idx = t; idx < 8 * 70; idx += 256) {
        int q = idx / 70, j = idx - q * 70;
        int b = (qg0 + q) >> 10;
        q0S[q][j] = preds[(b * 70 + j) * HWSZ + indS[q]];
    }
    #pragma unroll
    for (int q = 0; q < 8; q++) {
        int ind = indS[q];
        int xx = ind & 127, yy = ind >> 7;
        float pv = (t < 128) ? cole[xx * 128 + t] : rowe[yy * 128 + (t - 128)];
        g_qpos[(qg0 + q) * CHN + t] = pv;
    }
    __syncthreads();
    float acc[8] = {0.f,0.f,0.f,0.f,0.f,0.f,0.f,0.f};
    for (int j = 0; j < 70; j++) {
        float w = W1[j * CHN + t];
        #pragma unroll
        for (int q = 0; q < 8; q++) acc[q] += q0S[q][j] * w;
    }
    float bb = b1[t];
    #pragma unroll
    for (int q = 0; q < 8; q++) hidS[q][t] = gelu_tanh(acc[q] + bb);
    __syncthreads();
    float a2[8] = {0.f,0.f,0.f,0.f,0.f,0.f,0.f,0.f};
    for (int i = 0; i < CHN; i++) {
        float w = W2[i * CHN + t];
        #pragma unroll
        for (int q = 0; q < 8; q++) a2[q] += hidS[q][i] * w;
    }
    float b2v = b2[t];
    #pragma unroll
    for (int q = 0; q < 8; q++) g_q[(qg0 + q) * CHN + t] = a2[q] + b2v;
}

// ---------------- K4: batched so/aw GEMM + softmax (Q=16) ----------------
__global__ __launch_bounds__(256) void k_soaw(
    const float* __restrict__ soW, const float* __restrict__ sob,
    const float* __restrict__ awW, const float* __restrict__ awb) {
    __shared__ __align__(16) float qnS[16 * CHN];
    int t = threadIdx.x;
    int qg0 = blockIdx.x * 16;
    #pragma unroll
    for (int q = 0; q < 16; q++)
        qnS[q * CHN + t] = g_q[(qg0 + q) * CHN + t] + g_qpos[(qg0 + q) * CHN + t];
    __syncthreads();

    // so: 256 outputs
    {
        float as[16];
        #pragma unroll
        for (int q = 0; q < 16; q++) as[q] = 0.f;
        for (int i4 = 0; i4 < 64; i4++) {
            float w0 = soW[(4 * i4 + 0) * CHN + t];
            float w1 = soW[(4 * i4 + 1) * CHN + t];
            float w2 = soW[(4 * i4 + 2) * CHN + t];
            float w3 = soW[(4 * i4 + 3) * CHN + t];
            #pragma unroll
            for (int q = 0; q < 16; q++) {
                const float4 a = ((const float4*)(qnS + q * CHN))[i4];
                as[q] += a.x * w0 + a.y * w1 + a.z * w2 + a.w * w3;
            }
        }
        float sbv = sob[t];
        #pragma unroll
        for (int q = 0; q < 16; q++) g_so[(qg0 + q) * CHN + t] = as[q] + sbv;
    }

    // aw: 128 outputs + softmax over groups of 16 (per q,head)
    if (t < 128) {
        float aa[16];
        #pragma unroll
        for (int q = 0; q < 16; q++) aa[q] = 0.f;
        for (int i4 = 0; i4 < 64; i4++) {
            float w0 = awW[(4 * i4 + 0) * 128 + t];
            float w1 = awW[(4 * i4 + 1) * 128 + t];
            float w2 = awW[(4 * i4 + 2) * 128 + t];
            float w3 = awW[(4 * i4 + 3) * 128 + t];
            #pragma unroll
            for (int q = 0; q < 16; q++) {
                const float4 a = ((const float4*)(qnS + q * CHN))[i4];
                aa[q] += a.x * w0 + a.y * w1 + a.z * w2 + a.w * w3;
            }
        }
        float ab = awb[t];
        #pragma unroll
        for (int q = 0; q < 16; q++) {
            float vv = aa[q] + ab;
            float m = vv;
            #pragma unroll
            for (int o = 8; o > 0; o >>= 1)
                m = fmaxf(m, __shfl_xor_sync(0xffffffffu, m, o, 16));
            float e = expf(vv - m);
            float s = e;
            #pragma unroll
            for (int o = 8; o > 0; o >>= 1)
                s += __shfl_xor_sync(0xffffffffu, s, o, 16);
            g_aw[(qg0 + q) * 128 + t] = e / s;
        }
    }
}

// ---------------- K5: per-query dedup gather-aggregate (1 query / block) ----------------
__global__ __launch_bounds__(256) void k_gather() {
    __shared__ __align__(16) float hcoef[HSLOTS * 8];
    __shared__ __align__(16) float coefC[HSLOTS * 8];
    __shared__ int hkey[HSLOTS];
    __shared__ int cellList[HSLOTS];
    __shared__ int cntS;

    int t = threadIdx.x;
    int kq = blockIdx.x;
    int b = kq >> 10;

    // clear (HSLOTS == block size: one slot per thread)
    hkey[t] = -1;
    ((float4*)hcoef)[t * 2]     = make_float4(0.f, 0.f, 0.f, 0.f);
    ((float4*)hcoef)[t * 2 + 1] = make_float4(0.f, 0.f, 0.f, 0.f);
    if (t == 0) cntS = 0;
    __syncthreads();

    if (t < 128) {
        int ind = g_ind[kq];
        int h = t >> 4;
        int f = (t >> 2) & 3;
        float offx = g_so[kq * CHN + 2 * t];
        float offy = g_so[kq * CHN + 2 * t + 1];
        float aw = g_aw[kq * 128 + t];
        float xs = (float)(ind & 127) + offx;
        float ys = (float)(ind >> 7) + offy;
        float xf = floorf(xs), yf = floorf(ys);
        int x0 = (int)xf, y0 = (int)yf;
        float wx1 = xs - xf, wy1 = ys - yf;
        float wx0 = 1.f - wx1, wy0 = 1.f - wy1;
        int cxs[4] = {x0, x0 + 1, x0, x0 + 1};
        int cys[4] = {y0, y0, y0 + 1, y0 + 1};
        float cw[4] = {wx0 * wy0, wx1 * wy0, wx0 * wy1, wx1 * wy1};
        int base = (b * 4 + f) * HWSZ;
        float evs = 0.f;
        #pragma unroll
        for (int c = 0; c < 4; c++) {
            bool v = (cxs[c] >= 0) & (cxs[c] < 128) & (cys[c] >= 0) & (cys[c] < 128);
            if (v) {
                int key = base + cys[c] * 128 + cxs[c];
                float cf = aw * cw[c];
                evs += cf;
                unsigned s = ((unsigned)key * 2654435761u) >> 24;
                while (true) {
                    int prev = atomicCAS(&hkey[s], -1, key);
                    if (prev == -1 || prev == key) break;
                    s = (s + 1) & (HSLOTS - 1);
                }
                atomicAdd(&hcoef[s * 8 + h], cf);
            }
        }
        #pragma unroll
        for (int o = 8; o > 0; o >>= 1)
            evs += __shfl_xor_sync(0xffffffffu, evs, o, 16);
        if ((t & 15) == 0) g_bw[kq * 8 + h] = evs;
    }
    __syncthreads();

    // compact occupied slots into dense arrays
    {
        int key = hkey[t];
        if (key >= 0) {
            int pos = atomicAdd(&cntS, 1);
            cellList[pos] = key;
            ((float4*)coefC)[pos * 2]     = ((const float4*)hcoef)[t * 2];
            ((float4*)coefC)[pos * 2 + 1] = ((const float4*)hcoef)[t * 2 + 1];
        }
    }
    __syncthreads();
    int D = cntS;

    // aggregate: thread = channel; fully independent iterations
    float acc[8] = {0.f,0.f,0.f,0.f,0.f,0.f,0.f,0.f};
    for (int d = 0; d < D; d++) {
        int cell = cellList[d];
        float v = g_val[(size_t)cell * CHN + t];
        float4 c0 = ((const float4*)coefC)[d * 2];
        float4 c1 = ((const float4*)coefC)[d * 2 + 1];
        acc[0] += c0.x * v; acc[1] += c0.y * v; acc[2] += c0.z * v; acc[3] += c0.w * v;
        acc[4] += c1.x * v; acc[5] += c1.y * v; acc[6] += c1.z * v; acc[7] += c1.w * v;
    }
    #pragma unroll
    for (int h = 0; h < 8; h++)
        g_agg[((size_t)kq * 8 + h) * CHN + t] = acc[h];
}

// ---------------- K6: per-layer tail: vp + op + LN1 + FFN + LN2 (Q=16) ----------------
__device__ __forceinline__ void ln16(float v[16], float* redA, float* redB,
                                     float* mu, float* rs,
                                     const float* g, const float* b, int t) {
    int w = t >> 5, ln = t & 31;
    #pragma unroll
    for (int q = 0; q < 16; q++) {
        float s = v[q], s2 = v[q] * v[q];
        #pragma unroll
        for (int o = 16; o > 0; o >>= 1) {
            s  += __shfl_xor_sync(0xffffffffu, s, o);
            s2 += __shfl_xor_sync(0xffffffffu, s2, o);
        }
        if (ln == 0) { redA[q * 8 + w] = s; redB[q * 8 + w] = s2; }
    }
    __syncthreads();
    if (t < 16) {
        float s = 0.f, s2 = 0.f;
        #pragma unroll
        for (int k = 0; k < 8; k++) { s += redA[t * 8 + k]; s2 += redB[t * 8 + k]; }
        float m = s * (1.f / 256.f);
        mu[t] = m;
        rs[t] = rsqrtf(s2 * (1.f / 256.f) - m * m + 1e-5f);
    }
    __syncthreads();
    float gg = g[t], bb = b[t];
    #pragma unroll
    for (int q = 0; q < 16; q++) v[q] = (v[q] - mu[q]) * rs[q] * gg + bb;
}

__global__ __launch_bounds__(256) void k_tail(
    const float* __restrict__ vpW, const float* __restrict__ vpb,
    const float* __restrict__ opW, const float* __restrict__ opb,
    const float* __restrict__ g1, const float* __restrict__ b1,
    const float* __restrict__ W1, const float* __restrict__ fb1,
    const float* __restrict__ W2, const float* __restrict__ fb2,
    const float* __restrict__ g2, const float* __restrict__ b2) {
    __shared__ __align__(16) float qS[16 * CHN];
    __shared__ __align__(16) float buf[16 * CHN];
    __shared__ float redA[16 * 8], redB[16 * 8];
    __shared__ float mu[16], rs[16];
    int t = threadIdx.x;
    int qg0 = blockIdx.x * 16;
    int h = t >> 5;

    float v[16];

    // ---- vp: attn = agg @ vpW + bw * vpb -> buf ----
    #pragma unroll
    for (int q = 0; q < 16; q++) v[q] = 0.f;
    for (int i4 = 0; i4 < 64; i4++) {
        float w0 = vpW[(4 * i4 + 0) * CHN + t];
        float w1 = vpW[(4 * i4 + 1) * CHN + t];
        float w2 = vpW[(4 * i4 + 2) * CHN + t];
        float w3 = vpW[(4 * i4 + 3) * CHN + t];
        #pragma unroll
        for (int q = 0; q < 16; q++) {
            const float4 a = ((const float4*)(g_agg + ((size_t)(qg0 + q) * 8 + h) * CHN))[i4];
            v[q] += a.x * w0 + a.y * w1 + a.z * w2 + a.w * w3;
        }
    }
    {
        float vb = vpb[t];
        #pragma unroll
        for (int q = 0; q < 16; q++)
            buf[q * CHN + t] = v[q] + g_bw[(qg0 + q) * 8 + h] * vb;
    }
    __syncthreads();

    // ---- op: q += attn @ opW + opb ----
    #pragma unroll
    for (int q = 0; q < 16; q++) v[q] = g_q[(qg0 + q) * CHN + t];
    for (int i4 = 0; i4 < 64; i4++) {
        float w0 = opW[(4 * i4 + 0) * CHN + t];
        float w1 = opW[(4 * i4 + 1) * CHN + t];
        float w2 = opW[(4 * i4 + 2) * CHN + t];
        float w3 = opW[(4 * i4 + 3) * CHN + t];
        #pragma unroll
        for (int q = 0; q < 16; q++) {
            const float4 a = ((const float4*)(buf + q * CHN))[i4];
            v[q] += a.x * w0 + a.y * w1 + a.z * w2 + a.w * w3;
        }
    }
    {
        float ob = opb[t];
        #pragma unroll
        for (int q = 0; q < 16; q++) v[q] += ob;
    }
    __syncthreads();   // buf reused below

    // ---- LN1 ----
    ln16(v, redA, redB, mu, rs, g1, b1, t);
    #pragma unroll
    for (int q = 0; q < 16; q++) qS[q * CHN + t] = v[q];
    __syncthreads();

    // ---- FFN: 256 -> 1024 (relu) -> 256, hidden in 4 chunks; acc in v ----
    #pragma unroll
    for (int q = 0; q < 16; q++) v[q] = 0.f;
    for (int chunk = 0; chunk < 4; chunk++) {
        float hr[16];
        #pragma unroll
        for (int q = 0; q < 16; q++) hr[q] = 0.f;
        int j = chunk * CHN + t;
        for (int i4 = 0; i4 < 64; i4++) {
            float w0 = W1[(4 * i4 + 0) * 1024 + j];
            float w1 = W1[(4 * i4 + 1) * 1024 + j];
            float w2 = W1[(4 * i4 + 2) * 1024 + j];
            float w3 = W1[(4 * i4 + 3) * 1024 + j];
            #pragma unroll
            for (int q = 0; q < 16; q++) {
                const float4 a = ((const float4*)(qS + q * CHN))[i4];
                hr[q] += a.x * w0 + a.y * w1 + a.z * w2 + a.w * w3;
            }
        }
        float bj = fb1[j];
        #pragma unroll
        for (int q = 0; q < 16; q++) buf[q * CHN + t] = fmaxf(hr[q] + bj, 0.f);
        __syncthreads();
        for (int i4 = 0; i4 < 64; i4++) {
            float w0 = W2[(chunk * CHN + 4 * i4 + 0) * CHN + t];
            float w1 = W2[(chunk * CHN + 4 * i4 + 1) * CHN + t];
            float w2 = W2[(chunk * CHN + 4 * i4 + 2) * CHN + t];
            float w3 = W2[(chunk * CHN + 4 * i4 + 3) * CHN + t];
            #pragma unroll
            for (int q = 0; q < 16; q++) {
                const float4 a = ((const float4*)(buf + q * CHN))[i4];
                v[q] += a.x * w0 + a.y * w1 + a.z * w2 + a.w * w3;
            }
        }
        __syncthreads();
    }
    {
        float fb = fb2[t];
        #pragma unroll
        for (int q = 0; q < 16; q++) v[q] += qS[q * CHN + t] + fb;
    }

    // ---- LN2 ----
    ln16(v, redA, redB, mu, rs, g2, b2, t);
    #pragma unroll
    for (int q = 0; q < 16; q++) g_q[(qg0 + q) * CHN + t] = v[q];
}

// ---------------- K7/K8: zero-fill output, scatter queries ----------------
__global__ void k_zero(float4* __restrict__ out) {
    out[(size_t)blockIdx.x * 256 + threadIdx.x] = make_float4(0.f, 0.f, 0.f, 0.f);
}

__global__ void k_scatter(float* __restrict__ out) {
    int k = blockIdx.x, t = threadIdx.x;
    int b = k >> 10;
    int ind = g_ind[k];
    out[(b * CHN + t) * HWSZ + ind] = g_q[k * CHN + t];
}

// ---------------- launch ----------------
extern "C" void kernel_launch(void* const* d_in, const int* in_sizes, int n_in,
                              void* d_out, int out_size) {
    const float* x    = (const float*)d_in[0];
    const float* preds= (const float*)d_in[1];
    const float* hm   = (const float*)d_in[2];
    const float* mW1  = (const float*)d_in[3];
    const float* mb1  = (const float*)d_in[4];
    const float* mW2  = (const float*)d_in[5];
    const float* mb2  = (const float*)d_in[6];
    const float* tp   = (const float*)d_in[7];
    const float* rowe = (const float*)d_in[8];
    const float* cole = (const float*)d_in[9];
    const float* soW  = (const float*)d_in[10];
    const float* sob  = (const float*)d_in[11];
    const float* awW  = (const float*)d_in[12];
    const float* awb  = (const float*)d_in[13];
    const float* vpW  = (const float*)d_in[14];
    const float* vpb  = (const float*)d_in[15];
    const float* opW  = (const float*)d_in[16];
    const float* opb  = (const float*)d_in[17];
    const float* l1g  = (const float*)d_in[18];
    const float* l1b  = (const float*)d_in[19];
    const float* fW1  = (const float*)d_in[20];
    const float* fb1  = (const float*)d_in[21];
    const float* fW2  = (const float*)d_in[22];
    const float* fb2  = (const float*)d_in[23];
    const float* l2g  = (const float*)d_in[24];
    const float* l2b  = (const float*)d_in[25];
    float* out = (float*)d_out;

    k_transpose<<<dim3(4, 8, 1024), dim3(32, 32)>>>(x, tp);
    k_score<<<32, 1024>>>(hm);
    k_topk<<<2, 1024>>>();
    k_qinit<<<256, 256>>>(preds, mW1, mb1, mW2, mb2, rowe, cole);
    for (int l = 0; l < 3; l++) {
        k_soaw<<<128, 256>>>(soW + l * 65536, sob + l * 256,
                             awW + l * 32768, awb + l * 128);
        k_gather<<<2048, 256>>>();
        k_tail<<<128, 256>>>(vpW + l * 65536, vpb + l * 256,
                             opW + l * 65536, opb + l * 256,
                             l1g + l * 256, l1b + l * 256,
                             fW1 + l * 262144, fb1 + l * 1024,
                             fW2 + l * 262144, fb2 + l * 256,
                             l2g + l * 256, l2b + l * 256);
    }
    k_zero<<<8192, 256>>>((float4*)out);
    k_scatter<<<2048, 256>>>(out);
}

// round 5
// speedup vs baseline: 1.1000x; 1.1000x over previous
#include <cuda_runtime.h>
#include <math.h>

#define HWSZ 16384
#define CHN  256
#define KQ   1024
#define NQ   2048
#define HSLOTS 256

// ---------------- device scratch (static, allocation-free) ----------------
__device__ float    g_val[(size_t)2 * 4 * HWSZ * CHN];   // [b*4+f][y][x][c], +time_pos
__device__ unsigned g_keys[2 * HWSZ];
__device__ int      g_ind[NQ];
__device__ float    g_q[NQ * CHN];
__device__ float    g_qpos[NQ * CHN];
__device__ float    g_so[NQ * CHN];
__device__ float    g_aw[NQ * 128];
__device__ float    g_agg[(size_t)NQ * 8 * CHN];
__device__ float    g_bw[NQ * 8];

__device__ __forceinline__ float gelu_tanh(float v) {
    float c = 0.7978845608028654f * (v + 0.044715f * v * v * v);
    return 0.5f * v * (1.0f + tanhf(c));
}

// ---------------- K1: transpose x[b,f,c,y,x] -> g_val[b,f,y,x,c] (+time_pos) ----------------
__global__ void k_transpose(const float* __restrict__ x, const float* __restrict__ tp) {
    __shared__ float tile[32][33];
    int xt = blockIdx.x * 32;
    int ct = blockIdx.y * 32;
    int z  = blockIdx.z;
    int y  = z & 127;
    int bf = z >> 7;
    int f  = bf & 3;
    int tx = threadIdx.x, ty = threadIdx.y;
    tile[ty][tx] = x[((size_t)(bf * CHN + ct + ty) * 128 + y) * 128 + xt + tx];
    __syncthreads();
    g_val[((size_t)(bf * 128 + y) * 128 + xt + ty) * CHN + ct + tx] =
        tile[tx][ty] + tp[f * CHN + ct + tx];
}

// ---------------- K2a: channel-max score -> orderable keys ----------------
__global__ __launch_bounds__(1024) void k_score(const float* __restrict__ hm) {
    int i = blockIdx.x * 1024 + threadIdx.x;
    int b = i >> 14, cell = i & (HWSZ - 1);
    const float* hb = hm + (size_t)b * 10 * HWSZ + cell;
    float m = hb[0];
    #pragma unroll
    for (int c = 1; c < 10; c++) m = fmaxf(m, hb[c * HWSZ]);
    unsigned u = __float_as_uint(m);
    u = (u & 0x80000000u) ? ~u : (u | 0x80000000u);
    g_keys[i] = u;
}

// ---------------- K2b: radix top-1024 per batch ----------------
__global__ __launch_bounds__(1024) void k_topk() {
    int b = blockIdx.x, t = threadIdx.x;
    __shared__ unsigned hist[256];
    __shared__ unsigned sh[4];

    unsigned prefix = 0, r = KQ;
    for (int byte = 3; byte >= 0; byte--) {
        if (t < 256) hist[t] = 0;
        __syncthreads();
        int sh8 = byte * 8;
        unsigned pm = (byte == 3) ? 0u : (0xFFFFFFFFu << (8 * (byte + 1)));
        for (int i = t; i < HWSZ; i += 1024) {
            unsigned k = g_keys[b * HWSZ + i];
            if ((k & pm) == (prefix & pm)) atomicAdd(&hist[(k >> sh8) & 255u], 1u);
        }
        __syncthreads();
        if (t == 0) {
            unsigned cum = 0, d = 0;
            for (int dd = 255; dd >= 0; dd--) {
                if (cum + hist[dd] >= r) { d = (unsigned)dd; break; }
                cum += hist[dd];
            }
            sh[0] = d; sh[1] = r - cum;
        }
        __syncthreads();
        prefix |= sh[0] << sh8;
        r = sh[1];
        __syncthreads();
    }
    unsigned T = prefix;
    if (t == 0) { sh[2] = 0; sh[3] = 0; }
    __syncthreads();
    for (int i = t; i < HWSZ; i += 1024)
        if (g_keys[b * HWSZ + i] > T) atomicAdd(&sh[2], 1u);
    __syncthreads();
    unsigned cgt = sh[2];
    unsigned neq = KQ - cgt;
    __syncthreads();
    if (t == 0) sh[2] = 0;
    __syncthreads();
    for (int i = t; i < HWSZ; i += 1024) {
        unsigned k = g_keys[b * HWSZ + i];
        if (k > T) {
            unsigned s = atomicAdd(&sh[2], 1u);
            g_ind[b * KQ + s] = i;
        } else if (k == T) {
            unsigned e = atomicAdd(&sh[3], 1u);
            if (e < neq) g_ind[b * KQ + cgt + e] = i;
        }
    }
}

// ---------------- K3: query-init MLP + positional embed gather ----------------
__global__ __launch_bounds__(256) void k_qinit(
    const float* __restrict__ preds,
    const float* __restrict__ W1, const float* __restrict__ b1,
    const float* __restrict__ W2, const float* __restrict__ b2,
    const float* __restrict__ rowe, const float* __restrict__ cole) {
    __shared__ float q0S[8][70];
    __shared__ float hidS[8][CHN];
    __shared__ int   indS[8];
    int t = threadIdx.x;
    int qg0 = blockIdx.x * 8;
    if (t < 8) indS[t] = g_ind[qg0 + t];
    __syncthreads();
    for (int idx = t; idx < 8 * 70; idx += 256) {
        int q = idx / 70, j = idx - q * 70;
        int b = (qg0 + q) >> 10;
        q0S[q][j] = preds[(b * 70 + j) * HWSZ + indS[q]];
    }
    #pragma unroll
    for (int q = 0; q < 8; q++) {
        int ind = indS[q];
        int xx = ind & 127, yy = ind >> 7;
        float pv = (t < 128) ? cole[xx * 128 + t] : rowe[yy * 128 + (t - 128)];
        g_qpos[(qg0 + q) * CHN + t] = pv;
    }
    __syncthreads();
    float acc[8] = {0.f,0.f,0.f,0.f,0.f,0.f,0.f,0.f};
    for (int j = 0; j < 70; j++) {
        float w = W1[j * CHN + t];
        #pragma unroll
        for (int q = 0; q < 8; q++) acc[q] += q0S[q][j] * w;
    }
    float bb = b1[t];
    #pragma unroll
    for (int q = 0; q < 8; q++) hidS[q][t] = gelu_tanh(acc[q] + bb);
    __syncthreads();
    float a2[8] = {0.f,0.f,0.f,0.f,0.f,0.f,0.f,0.f};
    for (int i = 0; i < CHN; i++) {
        float w = W2[i * CHN + t];
        #pragma unroll
        for (int q = 0; q < 8; q++) a2[q] += hidS[q][i] * w;
    }
    float b2v = b2[t];
    #pragma unroll
    for (int q = 0; q < 8; q++) g_q[(qg0 + q) * CHN + t] = a2[q] + b2v;
}

// ---------------- K4: batched so/aw GEMM + softmax (Q=16) ----------------
__global__ __launch_bounds__(256) void k_soaw(
    const float* __restrict__ soW, const float* __restrict__ sob,
    const float* __restrict__ awW, const float* __restrict__ awb) {
    __shared__ __align__(16) float qnS[16 * CHN];
    int t = threadIdx.x;
    int qg0 = blockIdx.x * 16;
    #pragma unroll
    for (int q = 0; q < 16; q++)
        qnS[q * CHN + t] = g_q[(qg0 + q) * CHN + t] + g_qpos[(qg0 + q) * CHN + t];
    __syncthreads();

    {
        float as[16];
        #pragma unroll
        for (int q = 0; q < 16; q++) as[q] = 0.f;
        for (int i4 = 0; i4 < 64; i4++) {
            float w0 = soW[(4 * i4 + 0) * CHN + t];
            float w1 = soW[(4 * i4 + 1) * CHN + t];
            float w2 = soW[(4 * i4 + 2) * CHN + t];
            float w3 = soW[(4 * i4 + 3) * CHN + t];
            #pragma unroll
            for (int q = 0; q < 16; q++) {
                const float4 a = ((const float4*)(qnS + q * CHN))[i4];
                as[q] += a.x * w0 + a.y * w1 + a.z * w2 + a.w * w3;
            }
        }
        float sbv = sob[t];
        #pragma unroll
        for (int q = 0; q < 16; q++) g_so[(qg0 + q) * CHN + t] = as[q] + sbv;
    }

    if (t < 128) {
        float aa[16];
        #pragma unroll
        for (int q = 0; q < 16; q++) aa[q] = 0.f;
        for (int i4 = 0; i4 < 64; i4++) {
            float w0 = awW[(4 * i4 + 0) * 128 + t];
            float w1 = awW[(4 * i4 + 1) * 128 + t];
            float w2 = awW[(4 * i4 + 2) * 128 + t];
            float w3 = awW[(4 * i4 + 3) * 128 + t];
            #pragma unroll
            for (int q = 0; q < 16; q++) {
                const float4 a = ((const float4*)(qnS + q * CHN))[i4];
                aa[q] += a.x * w0 + a.y * w1 + a.z * w2 + a.w * w3;
            }
        }
        float ab = awb[t];
        #pragma unroll
        for (int q = 0; q < 16; q++) {
            float vv = aa[q] + ab;
            float m = vv;
            #pragma unroll
            for (int o = 8; o > 0; o >>= 1)
                m = fmaxf(m, __shfl_xor_sync(0xffffffffu, m, o, 16));
            float e = expf(vv - m);
            float s = e;
            #pragma unroll
            for (int o = 8; o > 0; o >>= 1)
                s += __shfl_xor_sync(0xffffffffu, s, o, 16);
            g_aw[(qg0 + q) * 128 + t] = e / s;
        }
    }
}

// ---------------- K5: per-query dedup gather-aggregate (1 query / block) ----------------
__global__ __launch_bounds__(256) void k_gather() {
    __shared__ __align__(16) float hcoef[HSLOTS * 8];
    __shared__ __align__(16) float coefC[HSLOTS * 8];
    __shared__ int hkey[HSLOTS];
    __shared__ int cellList[HSLOTS];
    __shared__ int cntS;

    int t = threadIdx.x;
    int kq = blockIdx.x;
    int b = kq >> 10;

    hkey[t] = -1;
    ((float4*)hcoef)[t * 2]     = make_float4(0.f, 0.f, 0.f, 0.f);
    ((float4*)hcoef)[t * 2 + 1] = make_float4(0.f, 0.f, 0.f, 0.f);
    if (t == 0) cntS = 0;
    __syncthreads();

    if (t < 128) {
        int ind = g_ind[kq];
        int h = t >> 4;
        int f = (t >> 2) & 3;
        float offx = g_so[kq * CHN + 2 * t];
        float offy = g_so[kq * CHN + 2 * t + 1];
        float aw = g_aw[kq * 128 + t];
        float xs = (float)(ind & 127) + offx;
        float ys = (float)(ind >> 7) + offy;
        float xf = floorf(xs), yf = floorf(ys);
        int x0 = (int)xf, y0 = (int)yf;
        float wx1 = xs - xf, wy1 = ys - yf;
        float wx0 = 1.f - wx1, wy0 = 1.f - wy1;
        int cxs[4] = {x0, x0 + 1, x0, x0 + 1};
        int cys[4] = {y0, y0, y0 + 1, y0 + 1};
        float cw[4] = {wx0 * wy0, wx1 * wy0, wx0 * wy1, wx1 * wy1};
        int base = (b * 4 + f) * HWSZ;
        float evs = 0.f;
        #pragma unroll
        for (int c = 0; c < 4; c++) {
            bool v = (cxs[c] >= 0) & (cxs[c] < 128) & (cys[c] >= 0) & (cys[c] < 128);
            if (v) {
                int key = base + cys[c] * 128 + cxs[c];
                float cf = aw * cw[c];
                evs += cf;
                unsigned s = ((unsigned)key * 2654435761u) >> 24;
                while (true) {
                    int prev = atomicCAS(&hkey[s], -1, key);
                    if (prev == -1 || prev == key) break;
                    s = (s + 1) & (HSLOTS - 1);
                }
                atomicAdd(&hcoef[s * 8 + h], cf);
            }
        }
        #pragma unroll
        for (int o = 8; o > 0; o >>= 1)
            evs += __shfl_xor_sync(0xffffffffu, evs, o, 16);
        if ((t & 15) == 0) g_bw[kq * 8 + h] = evs;
    }
    __syncthreads();

    {
        int key = hkey[t];
        if (key >= 0) {
            int pos = atomicAdd(&cntS, 1);
            cellList[pos] = key;
            ((float4*)coefC)[pos * 2]     = ((const float4*)hcoef)[t * 2];
            ((float4*)coefC)[pos * 2 + 1] = ((const float4*)hcoef)[t * 2 + 1];
        }
    }
    __syncthreads();
    int D = cntS;

    // aggregate: thread = channel; 4-wide unroll for MLP=4 (hide L2 latency)
    float acc[8] = {0.f,0.f,0.f,0.f,0.f,0.f,0.f,0.f};
    int d = 0;
    for (; d + 4 <= D; d += 4) {
        float v0 = g_val[(size_t)cellList[d + 0] * CHN + t];
        float v1 = g_val[(size_t)cellList[d + 1] * CHN + t];
        float v2 = g_val[(size_t)cellList[d + 2] * CHN + t];
        float v3 = g_val[(size_t)cellList[d + 3] * CHN + t];
        #pragma unroll
        for (int u = 0; u < 4; u++) {
            float v = (u == 0) ? v0 : (u == 1) ? v1 : (u == 2) ? v2 : v3;
            float4 c0 = ((const float4*)coefC)[(d + u) * 2];
            float4 c1 = ((const float4*)coefC)[(d + u) * 2 + 1];
            acc[0] += c0.x * v; acc[1] += c0.y * v; acc[2] += c0.z * v; acc[3] += c0.w * v;
            acc[4] += c1.x * v; acc[5] += c1.y * v; acc[6] += c1.z * v; acc[7] += c1.w * v;
        }
    }
    for (; d < D; d++) {
        float v = g_val[(size_t)cellList[d] * CHN + t];
        float4 c0 = ((const float4*)coefC)[d * 2];
        float4 c1 = ((const float4*)coefC)[d * 2 + 1];
        acc[0] += c0.x * v; acc[1] += c0.y * v; acc[2] += c0.z * v; acc[3] += c0.w * v;
        acc[4] += c1.x * v; acc[5] += c1.y * v; acc[6] += c1.z * v; acc[7] += c1.w * v;
    }
    #pragma unroll
    for (int h = 0; h < 8; h++)
        g_agg[((size_t)kq * 8 + h) * CHN + t] = acc[h];
}

// ---------------- K6: per-layer tail (512 threads, Q=16, thread=(ch,half)) ----------------
__device__ __forceinline__ void ln8h(float v[8], float* redA, float* redB,
                                     float* mu, float* rs,
                                     const float* g, const float* b,
                                     int ch, int grp, int t) {
    int w = (t >> 5) & 7;       // warp within half
    int ln = t & 31;
    #pragma unroll
    for (int q = 0; q < 8; q++) {
        float s = v[q], s2 = v[q] * v[q];
        #pragma unroll
        for (int o = 16; o > 0; o >>= 1) {
            s  += __shfl_xor_sync(0xffffffffu, s, o);
            s2 += __shfl_xor_sync(0xffffffffu, s2, o);
        }
        if (ln == 0) { redA[(grp * 8 + q) * 8 + w] = s; redB[(grp * 8 + q) * 8 + w] = s2; }
    }
    __syncthreads();
    if (t < 16) {
        float s = 0.f, s2 = 0.f;
        #pragma unroll
        for (int k = 0; k < 8; k++) { s += redA[t * 8 + k]; s2 += redB[t * 8 + k]; }
        float m = s * (1.f / 256.f);
        mu[t] = m;
        rs[t] = rsqrtf(s2 * (1.f / 256.f) - m * m + 1e-5f);
    }
    __syncthreads();
    float gg = g[ch], bb = b[ch];
    #pragma unroll
    for (int q = 0; q < 8; q++)
        v[q] = (v[q] - mu[grp * 8 + q]) * rs[grp * 8 + q] * gg + bb;
}

__global__ __launch_bounds__(512) void k_tail(
    const float* __restrict__ vpW, const float* __restrict__ vpb,
    const float* __restrict__ opW, const float* __restrict__ opb,
    const float* __restrict__ g1, const float* __restrict__ b1,
    const float* __restrict__ W1, const float* __restrict__ fb1,
    const float* __restrict__ W2, const float* __restrict__ fb2,
    const float* __restrict__ g2, const float* __restrict__ b2) {
    __shared__ __align__(16) float qS[16 * CHN];
    __shared__ __align__(16) float buf[16 * CHN];
    __shared__ float redA[16 * 8], redB[16 * 8];
    __shared__ float mu[16], rs[16];
    int t = threadIdx.x;
    int ch = t & 255;
    int grp = t >> 8;            // 0: queries 0-7, 1: queries 8-15
    int qb = grp * 8;
    int qg0 = blockIdx.x * 16;
    int h = ch >> 5;

    float v[8];

    // ---- vp: attn = agg @ vpW + bw * vpb -> buf ----
    #pragma unroll
    for (int q = 0; q < 8; q++) v[q] = 0.f;
    for (int i4 = 0; i4 < 64; i4++) {
        float w0 = vpW[(4 * i4 + 0) * CHN + ch];
        float w1 = vpW[(4 * i4 + 1) * CHN + ch];
        float w2 = vpW[(4 * i4 + 2) * CHN + ch];
        float w3 = vpW[(4 * i4 + 3) * CHN + ch];
        #pragma unroll
        for (int q = 0; q < 8; q++) {
            const float4 a = ((const float4*)(g_agg + ((size_t)(qg0 + qb + q) * 8 + h) * CHN))[i4];
            v[q] += a.x * w0 + a.y * w1 + a.z * w2 + a.w * w3;
        }
    }
    {
        float vb = vpb[ch];
        #pragma unroll
        for (int q = 0; q < 8; q++)
            buf[(qb + q) * CHN + ch] = v[q] + g_bw[(qg0 + qb + q) * 8 + h] * vb;
    }
    __syncthreads();

    // ---- op: q += attn @ opW + opb ----
    #pragma unroll
    for (int q = 0; q < 8; q++) v[q] = g_q[(qg0 + qb + q) * CHN + ch];
    for (int i4 = 0; i4 < 64; i4++) {
        float w0 = opW[(4 * i4 + 0) * CHN + ch];
        float w1 = opW[(4 * i4 + 1) * CHN + ch];
        float w2 = opW[(4 * i4 + 2) * CHN + ch];
        float w3 = opW[(4 * i4 + 3) * CHN + ch];
        #pragma unroll
        for (int q = 0; q < 8; q++) {
            const float4 a = ((const float4*)(buf + (qb + q) * CHN))[i4];
            v[q] += a.x * w0 + a.y * w1 + a.z * w2 + a.w * w3;
        }
    }
    {
        float ob = opb[ch];
        #pragma unroll
        for (int q = 0; q < 8; q++) v[q] += ob;
    }
    __syncthreads();

    // ---- LN1 ----
    ln8h(v, redA, redB, mu, rs, g1, b1, ch, grp, t);
    #pragma unroll
    for (int q = 0; q < 8; q++) qS[(qb + q) * CHN + ch] = v[q];
    __syncthreads();

    // ---- FFN: 256 -> 1024 (relu) -> 256 in 4 hidden chunks ----
    #pragma unroll
    for (int q = 0; q < 8; q++) v[q] = 0.f;
    for (int chunk = 0; chunk < 4; chunk++) {
        float hr[8] = {0.f,0.f,0.f,0.f,0.f,0.f,0.f,0.f};
        int j = chunk * CHN + ch;
        for (int i4 = 0; i4 < 64; i4++) {
            float w0 = W1[(4 * i4 + 0) * 1024 + j];
            float w1 = W1[(4 * i4 + 1) * 1024 + j];
            float w2 = W1[(4 * i4 + 2) * 1024 + j];
            float w3 = W1[(4 * i4 + 3) * 1024 + j];
            #pragma unroll
            for (int q = 0; q < 8; q++) {
                const float4 a = ((const float4*)(qS + (qb + q) * CHN))[i4];
                hr[q] += a.x * w0 + a.y * w1 + a.z * w2 + a.w * w3;
            }
        }
        float bj = fb1[j];
        #pragma unroll
        for (int q = 0; q < 8; q++) buf[(qb + q) * CHN + ch] = fmaxf(hr[q] + bj, 0.f);
        __syncthreads();
        for (int i4 = 0; i4 < 64; i4++) {
            float w0 = W2[(chunk * CHN + 4 * i4 + 0) * CHN + ch];
            float w1 = W2[(chunk * CHN + 4 * i4 + 1) * CHN + ch];
            float w2 = W2[(chunk * CHN + 4 * i4 + 2) * CHN + ch];
            float w3 = W2[(chunk * CHN + 4 * i4 + 3) * CHN + ch];
            #pragma unroll
            for (int q = 0; q < 8; q++) {
                const float4 a = ((const float4*)(buf + (qb + q) * CHN))[i4];
                v[q] += a.x * w0 + a.y * w1 + a.z * w2 + a.w * w3;
            }
        }
        __syncthreads();
    }
    {
        float fb = fb2[ch];
        #pragma unroll
        for (int q = 0; q < 8; q++) v[q] += qS[(qb + q) * CHN + ch] + fb;
    }

    // ---- LN2 ----
    ln8h(v, redA, redB, mu, rs, g2, b2, ch, grp, t);
    #pragma unroll
    for (int q = 0; q < 8; q++) g_q[(qg0 + qb + q) * CHN + ch] = v[q];
}

// ---------------- K7/K8: zero-fill output, scatter queries ----------------
__global__ void k_zero(float4* __restrict__ out) {
    out[(size_t)blockIdx.x * 256 + threadIdx.x] = make_float4(0.f, 0.f, 0.f, 0.f);
}

__global__ void k_scatter(float* __restrict__ out) {
    int k = blockIdx.x, t = threadIdx.x;
    int b = k >> 10;
    int ind = g_ind[k];
    out[(b * CHN + t) * HWSZ + ind] = g_q[k * CHN + t];
}

// ---------------- launch ----------------
extern "C" void kernel_launch(void* const* d_in, const int* in_sizes, int n_in,
                              void* d_out, int out_size) {
    const float* x    = (const float*)d_in[0];
    const float* preds= (const float*)d_in[1];
    const float* hm   = (const float*)d_in[2];
    const float* mW1  = (const float*)d_in[3];
    const float* mb1  = (const float*)d_in[4];
    const float* mW2  = (const float*)d_in[5];
    const float* mb2  = (const float*)d_in[6];
    const float* tp   = (const float*)d_in[7];
    const float* rowe = (const float*)d_in[8];
    const float* cole = (const float*)d_in[9];
    const float* soW  = (const float*)d_in[10];
    const float* sob  = (const float*)d_in[11];
    const float* awW  = (const float*)d_in[12];
    const float* awb  = (const float*)d_in[13];
    const float* vpW  = (const float*)d_in[14];
    const float* vpb  = (const float*)d_in[15];
    const float* opW  = (const float*)d_in[16];
    const float* opb  = (const float*)d_in[17];
    const float* l1g  = (const float*)d_in[18];
    const float* l1b  = (const float*)d_in[19];
    const float* fW1  = (const float*)d_in[20];
    const float* fb1  = (const float*)d_in[21];
    const float* fW2  = (const float*)d_in[22];
    const float* fb2  = (const float*)d_in[23];
    const float* l2g  = (const float*)d_in[24];
    const float* l2b  = (const float*)d_in[25];
    float* out = (float*)d_out;

    k_transpose<<<dim3(4, 8, 1024), dim3(32, 32)>>>(x, tp);
    k_score<<<32, 1024>>>(hm);
    k_topk<<<2, 1024>>>();
    k_qinit<<<256, 256>>>(preds, mW1, mb1, mW2, mb2, rowe, cole);
    for (int l = 0; l < 3; l++) {
        k_soaw<<<128, 256>>>(soW + l * 65536, sob + l * 256,
                             awW + l * 32768, awb + l * 128);
        k_gather<<<2048, 256>>>();
        k_tail<<<128, 512>>>(vpW + l * 65536, vpb + l * 256,
                             opW + l * 65536, opb + l * 256,
                             l1g + l * 256, l1b + l * 256,
                             fW1 + l * 262144, fb1 + l * 1024,
                             fW2 + l * 262144, fb2 + l * 256,
                             l2g + l * 256, l2b + l * 256);
    }
    k_zero<<<8192, 256>>>((float4*)out);
    k_scatter<<<2048, 256>>>(out);
}

// round 7
// speedup vs baseline: 1.2590x; 1.1445x over previous
#include <cuda_runtime.h>
#include <math.h>

#define HWSZ 16384
#define CHN  256
#define KQ   1024
#define NQ   2048
#define HSLOTS 256
#define TS 20   // transposed activation stride in floats (80B = 16B-aligned rows)

// ---------------- device scratch (static, allocation-free) ----------------
__device__ float    g_val[(size_t)2 * 4 * HWSZ * CHN];   // [b*4+f][y][x][c], +time_pos
__device__ unsigned g_keys[2 * HWSZ];
__device__ int      g_ind[NQ];
__device__ float    g_q[NQ * CHN];
__device__ float    g_qpos[NQ * CHN];
__device__ float    g_so[NQ * CHN];
__device__ float    g_aw[NQ * 128];
__device__ float    g_agg[(size_t)NQ * 8 * CHN];
__device__ float    g_bw[NQ * 8];

// ---------------- f32x2 packed helpers ----------------
typedef unsigned long long ull;
__device__ __forceinline__ ull pk2(float x, float y) {
    ull r;
    asm("mov.b64 %0, {%1, %2};" : "=l"(r) : "f"(x), "f"(y));
    return r;
}
__device__ __forceinline__ void upk2(ull v, float& x, float& y) {
    asm("mov.b64 {%0, %1}, %2;" : "=f"(x), "=f"(y) : "l"(v));
}
__device__ __forceinline__ ull fma2(ull a, ull b, ull c) {
    ull d;
    asm("fma.rn.f32x2 %0, %1, %2, %3;" : "=l"(d) : "l"(a), "l"(b), "l"(c));
    return d;
}

__device__ __forceinline__ float gelu_tanh(float v) {
    float c = 0.7978845608028654f * (v + 0.044715f * v * v * v);
    return 0.5f * v * (1.0f + tanhf(c));
}

// ---------------- K1: transpose x[b,f,c,y,x] -> g_val[b,f,y,x,c] (+time_pos) ----------------
__global__ void k_transpose(const float* __restrict__ x, const float* __restrict__ tp) {
    __shared__ float tile[32][33];
    int xt = blockIdx.x * 32;
    int ct = blockIdx.y * 32;
    int z  = blockIdx.z;
    int y  = z & 127;
    int bf = z >> 7;
    int f  = bf & 3;
    int tx = threadIdx.x, ty = threadIdx.y;
    tile[ty][tx] = x[((size_t)(bf * CHN + ct + ty) * 128 + y) * 128 + xt + tx];
    __syncthreads();
    g_val[((size_t)(bf * 128 + y) * 128 + xt + ty) * CHN + ct + tx] =
        tile[tx][ty] + tp[f * CHN + ct + tx];
}

// ---------------- K2a: channel-max score -> orderable keys ----------------
__global__ __launch_bounds__(1024) void k_score(const float* __restrict__ hm) {
    int i = blockIdx.x * 1024 + threadIdx.x;
    int b = i >> 14, cell = i & (HWSZ - 1);
    const float* hb = hm + (size_t)b * 10 * HWSZ + cell;
    float m = hb[0];
    #pragma unroll
    for (int c = 1; c < 10; c++) m = fmaxf(m, hb[c * HWSZ]);
    unsigned u = __float_as_uint(m);
    u = (u & 0x80000000u) ? ~u : (u | 0x80000000u);
    g_keys[i] = u;
}

// ---------------- K2b: radix top-1024 per batch ----------------
__global__ __launch_bounds__(1024) void k_topk() {
    int b = blockIdx.x, t = threadIdx.x;
    __shared__ unsigned hist[256];
    __shared__ unsigned sh[4];

    unsigned prefix = 0, r = KQ;
    for (int byte = 3; byte >= 0; byte--) {
        if (t < 256) hist[t] = 0;
        __syncthreads();
        int sh8 = byte * 8;
        unsigned pm = (byte == 3) ? 0u : (0xFFFFFFFFu << (8 * (byte + 1)));
        for (int i = t; i < HWSZ; i += 1024) {
            unsigned k = g_keys[b * HWSZ + i];
            if ((k & pm) == (prefix & pm)) atomicAdd(&hist[(k >> sh8) & 255u], 1u);
        }
        __syncthreads();
        if (t == 0) {
            unsigned cum = 0, d = 0;
            for (int dd = 255; dd >= 0; dd--) {
                if (cum + hist[dd] >= r) { d = (unsigned)dd; break; }
                cum += hist[dd];
            }
            sh[0] = d; sh[1] = r - cum;
        }
        __syncthreads();
        prefix |= sh[0] << sh8;
        r = sh[1];
        __syncthreads();
    }
    unsigned T = prefix;
    if (t == 0) { sh[2] = 0; sh[3] = 0; }
    __syncthreads();
    for (int i = t; i < HWSZ; i += 1024)
        if (g_keys[b * HWSZ + i] > T) atomicAdd(&sh[2], 1u);
    __syncthreads();
    unsigned cgt = sh[2];
    unsigned neq = KQ - cgt;
    __syncthreads();
    if (t == 0) sh[2] = 0;
    __syncthreads();
    for (int i = t; i < HWSZ; i += 1024) {
        unsigned k = g_keys[b * HWSZ + i];
        if (k > T) {
            unsigned s = atomicAdd(&sh[2], 1u);
            g_ind[b * KQ + s] = i;
        } else if (k == T) {
            unsigned e = atomicAdd(&sh[3], 1u);
            if (e < neq) g_ind[b * KQ + cgt + e] = i;
        }
    }
}

// ---------------- K3: query-init MLP + positional embed gather ----------------
__global__ __launch_bounds__(256) void k_qinit(
    const float* __restrict__ preds,
    const float* __restrict__ W1, const float* __restrict__ b1,
    const float* __restrict__ W2, const float* __restrict__ b2,
    const float* __restrict__ rowe, const float* __restrict__ cole) {
    __shared__ float q0S[8][70];
    __shared__ float hidS[8][CHN];
    __shared__ int   indS[8];
    int t = threadIdx.x;
    int qg0 = blockIdx.x * 8;
    if (t < 8) indS[t] = g_ind[qg0 + t];
    __syncthreads();
    for (int idx = t; idx < 8 * 70; idx += 256) {
        int q = idx / 70, j = idx - q * 70;
        int b = (qg0 + q) >> 10;
        q0S[q][j] = preds[(b * 70 + j) * HWSZ + indS[q]];
    }
    #pragma unroll
    for (int q = 0; q < 8; q++) {
        int ind = indS[q];
        int xx = ind & 127, yy = ind >> 7;
        float pv = (t < 128) ? cole[xx * 128 + t] : rowe[yy * 128 + (t - 128)];
        g_qpos[(qg0 + q) * CHN + t] = pv;
    }
    __syncthreads();
    float acc[8] = {0.f,0.f,0.f,0.f,0.f,0.f,0.f,0.f};
    for (int j = 0; j < 70; j++) {
        float w = W1[j * CHN + t];
        #pragma unroll
        for (int q = 0; q < 8; q++) acc[q] += q0S[q][j] * w;
    }
    float bb = b1[t];
    #pragma unroll
    for (int q = 0; q < 8; q++) hidS[q][t] = gelu_tanh(acc[q] + bb);
    __syncthreads();
    float a2[8] = {0.f,0.f,0.f,0.f,0.f,0.f,0.f,0.f};
    for (int i = 0; i < CHN; i++) {
        float w = W2[i * CHN + t];
        #pragma unroll
        for (int q = 0; q < 8; q++) a2[q] += hidS[q][i] * w;
    }
    float b2v = b2[t];
    #pragma unroll
    for (int q = 0; q < 8; q++) g_q[(qg0 + q) * CHN + t] = a2[q] + b2v;
}

// ---------------- K4: so/aw GEMM + softmax, f32x2, concurrent warps (512t, Q=16) ----------------
__global__ __launch_bounds__(512) void k_soaw(
    const float* __restrict__ soW, const float* __restrict__ sob,
    const float* __restrict__ awW, const float* __restrict__ awb) {
    __shared__ __align__(16) float qnT[256 * TS];   // [i][q] transposed activations
    int t = threadIdx.x;
    int qg0 = blockIdx.x * 16;

    for (int idx = t; idx < 4096; idx += 512) {
        int q = idx & 15, i = idx >> 4;
        qnT[i * TS + q] = g_q[(qg0 + q) * CHN + i] + g_qpos[(qg0 + q) * CHN + i];
    }
    __syncthreads();

    if (t < 256) {
        // so: out channel = t, 16 queries as 8 f32x2 pairs
        ull acc2[8];
        #pragma unroll
        for (int p = 0; p < 8; p++) acc2[p] = pk2(0.f, 0.f);
        #pragma unroll 4
        for (int i = 0; i < 256; i++) {
            ull w2 = pk2(soW[i * CHN + t], soW[i * CHN + t]);
            const float4 a0 = *(const float4*)&qnT[i * TS + 0];
            const float4 a1 = *(const float4*)&qnT[i * TS + 4];
            const float4 a2_ = *(const float4*)&qnT[i * TS + 8];
            const float4 a3 = *(const float4*)&qnT[i * TS + 12];
            acc2[0] = fma2(pk2(a0.x, a0.y), w2, acc2[0]);
            acc2[1] = fma2(pk2(a0.z, a0.w), w2, acc2[1]);
            acc2[2] = fma2(pk2(a1.x, a1.y), w2, acc2[2]);
            acc2[3] = fma2(pk2(a1.z, a1.w), w2, acc2[3]);
            acc2[4] = fma2(pk2(a2_.x, a2_.y), w2, acc2[4]);
            acc2[5] = fma2(pk2(a2_.z, a2_.w), w2, acc2[5]);
            acc2[6] = fma2(pk2(a3.x, a3.y), w2, acc2[6]);
            acc2[7] = fma2(pk2(a3.z, a3.w), w2, acc2[7]);
        }
        float sbv = sob[t];
        #pragma unroll
        for (int p = 0; p < 8; p++) {
            float lo, hi;
            upk2(acc2[p], lo, hi);
            g_so[(qg0 + 2 * p) * CHN + t]     = lo + sbv;
            g_so[(qg0 + 2 * p + 1) * CHN + t] = hi + sbv;
        }
    } else if (t < 384) {
        // aw: out channel = t-256 (128 outs), 16 queries; then 16-wide softmax
        int c = t - 256;
        ull acc2[8];
        #pragma unroll
        for (int p = 0; p < 8; p++) acc2[p] = pk2(0.f, 0.f);
        #pragma unroll 4
        for (int i = 0; i < 256; i++) {
            ull w2 = pk2(awW[i * 128 + c], awW[i * 128 + c]);
            const float4 a0 = *(const float4*)&qnT[i * TS + 0];
            const float4 a1 = *(const float4*)&qnT[i * TS + 4];
            const float4 a2_ = *(const float4*)&qnT[i * TS + 8];
            const float4 a3 = *(const float4*)&qnT[i * TS + 12];
            acc2[0] = fma2(pk2(a0.x, a0.y), w2, acc2[0]);
            acc2[1] = fma2(pk2(a0.z, a0.w), w2, acc2[1]);
            acc2[2] = fma2(pk2(a1.x, a1.y), w2, acc2[2]);
            acc2[3] = fma2(pk2(a1.z, a1.w), w2, acc2[3]);
            acc2[4] = fma2(pk2(a2_.x, a2_.y), w2, acc2[4]);
            acc2[5] = fma2(pk2(a2_.z, a2_.w), w2, acc2[5]);
            acc2[6] = fma2(pk2(a3.x, a3.y), w2, acc2[6]);
            acc2[7] = fma2(pk2(a3.z, a3.w), w2, acc2[7]);
        }
        float ab = awb[c];
        float av[16];
        #pragma unroll
        for (int p = 0; p < 8; p++) {
            upk2(acc2[p], av[2 * p], av[2 * p + 1]);
            av[2 * p] += ab; av[2 * p + 1] += ab;
        }
        #pragma unroll
        for (int q = 0; q < 16; q++) {
            float vv = av[q];
            float m = vv;
            #pragma unroll
            for (int o = 8; o > 0; o >>= 1)
                m = fmaxf(m, __shfl_xor_sync(0xffffffffu, m, o, 16));
            float e = expf(vv - m);
            float s = e;
            #pragma unroll
            for (int o = 8; o > 0; o >>= 1)
                s += __shfl_xor_sync(0xffffffffu, s, o, 16);
            g_aw[(qg0 + q) * 128 + c] = e / s;
        }
    }
}

// ---------------- K5: per-query dedup gather-aggregate (1 query / block) ----------------
__global__ __launch_bounds__(256) void k_gather() {
    __shared__ __align__(16) float hcoef[HSLOTS * 8];
    __shared__ __align__(16) float coefC[HSLOTS * 8];
    __shared__ int hkey[HSLOTS];
    __shared__ int cellList[HSLOTS];
    __shared__ int cntS;

    int t = threadIdx.x;
    int kq = blockIdx.x;
    int b = kq >> 10;

    hkey[t] = -1;
    ((float4*)hcoef)[t * 2]     = make_float4(0.f, 0.f, 0.f, 0.f);
    ((float4*)hcoef)[t * 2 + 1] = make_float4(0.f, 0.f, 0.f, 0.f);
    if (t == 0) cntS = 0;
    __syncthreads();

    if (t < 128) {
        int ind = g_ind[kq];
        int h = t >> 4;
        int f = (t >> 2) & 3;
        float offx = g_so[kq * CHN + 2 * t];
        float offy = g_so[kq * CHN + 2 * t + 1];
        float aw = g_aw[kq * 128 + t];
        float xs = (float)(ind & 127) + offx;
        float ys = (float)(ind >> 7) + offy;
        float xf = floorf(xs), yf = floorf(ys);
        int x0 = (int)xf, y0 = (int)yf;
        float wx1 = xs - xf, wy1 = ys - yf;
        float wx0 = 1.f - wx1, wy0 = 1.f - wy1;
        int cxs[4] = {x0, x0 + 1, x0, x0 + 1};
        int cys[4] = {y0, y0, y0 + 1, y0 + 1};
        float cw[4] = {wx0 * wy0, wx1 * wy0, wx0 * wy1, wx1 * wy1};
        int base = (b * 4 + f) * HWSZ;
        float evs = 0.f;
        #pragma unroll
        for (int c = 0; c < 4; c++) {
            bool v = (cxs[c] >= 0) & (cxs[c] < 128) & (cys[c] >= 0) & (cys[c] < 128);
            if (v) {
                int key = base + cys[c] * 128 + cxs[c];
                float cf = aw * cw[c];
                evs += cf;
                unsigned s = ((unsigned)key * 2654435761u) >> 24;
                while (true) {
                    int prev = atomicCAS(&hkey[s], -1, key);
                    if (prev == -1 || prev == key) break;
                    s = (s + 1) & (HSLOTS - 1);
                }
                atomicAdd(&hcoef[s * 8 + h], cf);
            }
        }
        #pragma unroll
        for (int o = 8; o > 0; o >>= 1)
            evs += __shfl_xor_sync(0xffffffffu, evs, o, 16);
        if ((t & 15) == 0) g_bw[kq * 8 + h] = evs;
    }
    __syncthreads();

    {
        int key = hkey[t];
        if (key >= 0) {
            int pos = atomicAdd(&cntS, 1);
            cellList[pos] = key;
            ((float4*)coefC)[pos * 2]     = ((const float4*)hcoef)[t * 2];
            ((float4*)coefC)[pos * 2 + 1] = ((const float4*)hcoef)[t * 2 + 1];
        }
    }
    __syncthreads();
    int D = cntS;

    // aggregate: thread = channel; f32x2, 4-wide LDG batching (MLP=4)
    ull acc2[4];
    #pragma unroll
    for (int p = 0; p < 4; p++) acc2[p] = pk2(0.f, 0.f);
    int d = 0;
    for (; d + 4 <= D; d += 4) {
        float v0 = g_val[(size_t)cellList[d + 0] * CHN + t];
        float v1 = g_val[(size_t)cellList[d + 1] * CHN + t];
        float v2 = g_val[(size_t)cellList[d + 2] * CHN + t];
        float v3 = g_val[(size_t)cellList[d + 3] * CHN + t];
        #pragma unroll
        for (int u = 0; u < 4; u++) {
            float vv = (u == 0) ? v0 : (u == 1) ? v1 : (u == 2) ? v2 : v3;
            ull v2p = pk2(vv, vv);
            const float4 c0 = ((const float4*)coefC)[(d + u) * 2];
            const float4 c1 = ((const float4*)coefC)[(d + u) * 2 + 1];
            acc2[0] = fma2(pk2(c0.x, c0.y), v2p, acc2[0]);
            acc2[1] = fma2(pk2(c0.z, c0.w), v2p, acc2[1]);
            acc2[2] = fma2(pk2(c1.x, c1.y), v2p, acc2[2]);
            acc2[3] = fma2(pk2(c1.z, c1.w), v2p, acc2[3]);
        }
    }
    for (; d < D; d++) {
        float vv = g_val[(size_t)cellList[d] * CHN + t];
        ull v2p = pk2(vv, vv);
        const float4 c0 = ((const float4*)coefC)[d * 2];
        const float4 c1 = ((const float4*)coefC)[d * 2 + 1];
        acc2[0] = fma2(pk2(c0.x, c0.y), v2p, acc2[0]);
        acc2[1] = fma2(pk2(c0.z, c0.w), v2p, acc2[1]);
        acc2[2] = fma2(pk2(c1.x, c1.y), v2p, acc2[2]);
        acc2[3] = fma2(pk2(c1.z, c1.w), v2p, acc2[3]);
    }
    #pragma unroll
    for (int p = 0; p < 4; p++) {
        float lo, hi;
        upk2(acc2[p], lo, hi);
        g_agg[((size_t)kq * 8 + 2 * p) * CHN + t]     = lo;
        g_agg[((size_t)kq * 8 + 2 * p + 1) * CHN + t] = hi;
    }
}

// ---------------- K6: per-layer tail: vp + op + LN1 + FFN + LN2 (512t, Q=16, f32x2) ----------------
__device__ __forceinline__ void ln8h(float v[8], float* redA, float* redB,
                                     float* mu, float* rs,
                                     const float* g, const float* b,
                                     int ch, int grp, int t) {
    int w = (t >> 5) & 7;
    int ln = t & 31;
    #pragma unroll
    for (int q = 0; q < 8; q++) {
        float s = v[q], s2 = v[q] * v[q];
        #pragma unroll
        for (int o = 16; o > 0; o >>= 1) {
            s  += __shfl_xor_sync(0xffffffffu, s, o);
            s2 += __shfl_xor_sync(0xffffffffu, s2, o);
        }
        if (ln == 0) { redA[(grp * 8 + q) * 8 + w] = s; redB[(grp * 8 + q) * 8 + w] = s2; }
    }
    __syncthreads();
    if (t < 16) {
        float s = 0.f, s2 = 0.f;
        #pragma unroll
        for (int k = 0; k < 8; k++) { s += redA[t * 8 + k]; s2 += redB[t * 8 + k]; }
        float m = s * (1.f / 256.f);
        mu[t] = m;
        rs[t] = rsqrtf(s2 * (1.f / 256.f) - m * m + 1e-5f);
    }
    __syncthreads();
    float gg = g[ch], bb = b[ch];
    #pragma unroll
    for (int q = 0; q < 8; q++)
        v[q] = (v[q] - mu[grp * 8 + q]) * rs[grp * 8 + q] * gg + bb;
}

__global__ __launch_bounds__(512) void k_tail(
    const float* __restrict__ vpW, const float* __restrict__ vpb,
    const float* __restrict__ opW, const float* __restrict__ opb,
    const float* __restrict__ g1, const float* __restrict__ b1,
    const float* __restrict__ W1, const float* __restrict__ fb1,
    const float* __restrict__ W2, const float* __restrict__ fb2,
    const float* __restrict__ g2, const float* __restrict__ b2) {
    __shared__ __align__(16) float bufT[256 * TS];   // transposed activations [i][q]
    __shared__ __align__(16) float qST[256 * TS];    // LN1 out (FFN input + residual)
    __shared__ float redA[16 * 8], redB[16 * 8];
    __shared__ float mu[16], rs[16];
    int t = threadIdx.x;
    int ch = t & 255;
    int grp = t >> 8;            // 0: queries 0-7, 1: queries 8-15
    int qb = grp * 8;
    int qg0 = blockIdx.x * 16;
    int h = ch >> 5;

    float v[8];

    // ---- vp (scalar; activations in gmem) ----
    #pragma unroll
    for (int q = 0; q < 8; q++) v[q] = 0.f;
    for (int i4 = 0; i4 < 64; i4++) {
        float w0 = vpW[(4 * i4 + 0) * CHN + ch];
        float w1 = vpW[(4 * i4 + 1) * CHN + ch];
        float w2 = vpW[(4 * i4 + 2) * CHN + ch];
        float w3 = vpW[(4 * i4 + 3) * CHN + ch];
        #pragma unroll
        for (int q = 0; q < 8; q++) {
            const float4 a = ((const float4*)(g_agg + ((size_t)(qg0 + qb + q) * 8 + h) * CHN))[i4];
            v[q] += a.x * w0 + a.y * w1 + a.z * w2 + a.w * w3;
        }
    }
    {
        float vb = vpb[ch];
        #pragma unroll
        for (int q = 0; q < 8; q++)
            bufT[ch * TS + qb + q] = v[q] + g_bw[(qg0 + qb + q) * 8 + h] * vb;
    }
    __syncthreads();

    // ---- op: q += attn @ opW + opb (f32x2) ----
    ull acc2[4];
    #pragma unroll
    for (int p = 0; p < 4; p++)
        acc2[p] = pk2(g_q[(qg0 + qb + 2 * p) * CHN + ch], g_q[(qg0 + qb + 2 * p + 1) * CHN + ch]);
    #pragma unroll 4
    for (int i = 0; i < 256; i++) {
        float w = opW[i * CHN + ch];
        ull w2 = pk2(w, w);
        const float4 a0 = *(const float4*)&bufT[i * TS + qb];
        const float4 a1 = *(const float4*)&bufT[i * TS + qb + 4];
        acc2[0] = fma2(pk2(a0.x, a0.y), w2, acc2[0]);
        acc2[1] = fma2(pk2(a0.z, a0.w), w2, acc2[1]);
        acc2[2] = fma2(pk2(a1.x, a1.y), w2, acc2[2]);
        acc2[3] = fma2(pk2(a1.z, a1.w), w2, acc2[3]);
    }
    {
        float ob = opb[ch];
        #pragma unroll
        for (int p = 0; p < 4; p++) {
            upk2(acc2[p], v[2 * p], v[2 * p + 1]);
            v[2 * p] += ob; v[2 * p + 1] += ob;
        }
    }

    // ---- LN1 (internal syncs also fence bufT reuse) ----
    ln8h(v, redA, redB, mu, rs, g1, b1, ch, grp, t);
    #pragma unroll
    for (int q = 0; q < 8; q++) qST[ch * TS + qb + q] = v[q];
    __syncthreads();

    // ---- FFN: 256 -> 1024 (relu) -> 256 in 4 hidden chunks (f32x2) ----
    ull o2[4];
    #pragma unroll
    for (int p = 0; p < 4; p++) o2[p] = pk2(0.f, 0.f);
    for (int chunk = 0; chunk < 4; chunk++) {
        ull h2[4];
        #pragma unroll
        for (int p = 0; p < 4; p++) h2[p] = pk2(0.f, 0.f);
        int j = chunk * CHN + ch;
        #pragma unroll 4
        for (int i = 0; i < 256; i++) {
            float w = W1[i * 1024 + j];
            ull w2 = pk2(w, w);
            const float4 a0 = *(const float4*)&qST[i * TS + qb];
            const float4 a1 = *(const float4*)&qST[i * TS + qb + 4];
            h2[0] = fma2(pk2(a0.x, a0.y), w2, h2[0]);
            h2[1] = fma2(pk2(a0.z, a0.w), w2, h2[1]);
            h2[2] = fma2(pk2(a1.x, a1.y), w2, h2[2]);
            h2[3] = fma2(pk2(a1.z, a1.w), w2, h2[3]);
        }
        float bj = fb1[j];
        #pragma unroll
        for (int p = 0; p < 4; p++) {
            float lo, hi;
            upk2(h2[p], lo, hi);
            bufT[ch * TS + qb + 2 * p]     = fmaxf(lo + bj, 0.f);
            bufT[ch * TS + qb + 2 * p + 1] = fmaxf(hi + bj, 0.f);
        }
        __syncthreads();
        #pragma unroll 4
        for (int i = 0; i < 256; i++) {
            float w = W2[(chunk * CHN + i) * CHN + ch];
            ull w2 = pk2(w, w);
            const float4 a0 = *(const float4*)&bufT[i * TS + qb];
            const float4 a1 = *(const float4*)&bufT[i * TS + qb + 4];
            o2[0] = fma2(pk2(a0.x, a0.y), w2, o2[0]);
            o2[1] = fma2(pk2(a0.z, a0.w), w2, o2[1]);
            o2[2] = fma2(pk2(a1.x, a1.y), w2, o2[2]);
            o2[3] = fma2(pk2(a1.z, a1.w), w2, o2[3]);
        }
        __syncthreads();
    }
    {
        float fb = fb2[ch];
        #pragma unroll
        for (int p = 0; p < 4; p++) {
            float lo, hi;
            upk2(o2[p], lo, hi);
            v[2 * p]     = lo + qST[ch * TS + qb + 2 * p] + fb;
            v[2 * p + 1] = hi + qST[ch * TS + qb + 2 * p + 1] + fb;
        }
    }

    // ---- LN2 ----
    ln8h(v, redA, redB, mu, rs, g2, b2, ch, grp, t);
    #pragma unroll
    for (int q = 0; q < 8; q++) g_q[(qg0 + qb + q) * CHN + ch] = v[q];
}

// ---------------- K7/K8: zero-fill output, scatter queries ----------------
__global__ void k_zero(float4* __restrict__ out) {
    out[(size_t)blockIdx.x * 256 + threadIdx.x] = make_float4(0.f, 0.f, 0.f, 0.f);
}

__global__ void k_scatter(float* __restrict__ out) {
    int k = blockIdx.x, t = threadIdx.x;
    int b = k >> 10;
    int ind = g_ind[k];
    out[(b * CHN + t) * HWSZ + ind] = g_q[k * CHN + t];
}

// ---------------- launch ----------------
extern "C" void kernel_launch(void* const* d_in, const int* in_sizes, int n_in,
                              void* d_out, int out_size) {
    const float* x    = (const float*)d_in[0];
    const float* preds= (const float*)d_in[1];
    const float* hm   = (const float*)d_in[2];
    const float* mW1  = (const float*)d_in[3];
    const float* mb1  = (const float*)d_in[4];
    const float* mW2  = (const float*)d_in[5];
    const float* mb2  = (const float*)d_in[6];
    const float* tp   = (const float*)d_in[7];
    const float* rowe = (const float*)d_in[8];
    const float* cole = (const float*)d_in[9];
    const float* soW  = (const float*)d_in[10];
    const float* sob  = (const float*)d_in[11];
    const float* awW  = (const float*)d_in[12];
    const float* awb  = (const float*)d_in[13];
    const float* vpW  = (const float*)d_in[14];
    const float* vpb  = (const float*)d_in[15];
    const float* opW  = (const float*)d_in[16];
    const float* opb  = (const float*)d_in[17];
    const float* l1g  = (const float*)d_in[18];
    const float* l1b  = (const float*)d_in[19];
    const float* fW1  = (const float*)d_in[20];
    const float* fb1  = (const float*)d_in[21];
    const float* fW2  = (const float*)d_in[22];
    const float* fb2  = (const float*)d_in[23];
    const float* l2g  = (const float*)d_in[24];
    const float* l2b  = (const float*)d_in[25];
    float* out = (float*)d_out;

    k_transpose<<<dim3(4, 8, 1024), dim3(32, 32)>>>(x, tp);
    k_score<<<32, 1024>>>(hm);
    k_topk<<<2, 1024>>>();
    k_qinit<<<256, 256>>>(preds, mW1, mb1, mW2, mb2, rowe, cole);
    for (int l = 0; l < 3; l++) {
        k_soaw<<<128, 512>>>(soW + l * 65536, sob + l * 256,
                             awW + l * 32768, awb + l * 128);
        k_gather<<<2048, 256>>>();
        k_tail<<<128, 512>>>(vpW + l * 65536, vpb + l * 256,
                             opW + l * 65536, opb + l * 256,
                             l1g + l * 256, l1b + l * 256,
                             fW1 + l * 262144, fb1 + l * 1024,
                             fW2 + l * 262144, fb2 + l * 256,
                             l2g + l * 256, l2b + l * 256);
    }
    k_zero<<<8192, 256>>>((float4*)out);
    k_scatter<<<2048, 256>>>(out);
}